// round 1
// baseline (speedup 1.0000x reference)
#include <cuda_runtime.h>
#include <cstddef>

// Problem constants (fixed by setup_inputs)
#define SEQ   4096
#define DMODEL 512
#define NHEAD 8
#define DK    64

// Scratch (static device globals — no allocation in kernel_launch)
__device__ float g_Q[2 * SEQ * DMODEL];
__device__ float g_K[2 * SEQ * DMODEL];
__device__ float g_V[2 * SEQ * DMODEL];
__device__ float g_C[2 * SEQ * DMODEL];

// ---------------------------------------------------------------------------
// GEMM: C[m][n] = sum_k A[m][k] * W[n][k] + bias[n]   (torch Linear: x @ W.T + b)
// A: [M,K] row-major, W: [N,K] row-major. 128x128 block, BK=16, 8x8/thread.
// ---------------------------------------------------------------------------
__global__ __launch_bounds__(256)
void gemm_bias_kernel(const float* __restrict__ A, const float* __restrict__ W,
                      const float* __restrict__ bias, float* __restrict__ C,
                      int M, int N, int K)
{
    __shared__ float As[16][128];
    __shared__ float Ws[16][128];

    const int tid  = threadIdx.x;
    const int brow = blockIdx.y * 128;
    const int bcol = blockIdx.x * 128;
    const int tr   = (tid / 16) * 8;
    const int tc   = (tid % 16) * 8;

    const int lr = tid / 4;          // 0..63
    const int lc = (tid % 4) * 4;    // 0,4,8,12

    float acc[8][8];
#pragma unroll
    for (int i = 0; i < 8; i++)
#pragma unroll
        for (int j = 0; j < 8; j++) acc[i][j] = 0.f;

    for (int k0 = 0; k0 < K; k0 += 16) {
#pragma unroll
        for (int i = 0; i < 2; i++) {
            int r = lr + i * 64;
            float4 va = *reinterpret_cast<const float4*>(A + (size_t)(brow + r) * K + k0 + lc);
            As[lc + 0][r] = va.x; As[lc + 1][r] = va.y;
            As[lc + 2][r] = va.z; As[lc + 3][r] = va.w;
            float4 vw = *reinterpret_cast<const float4*>(W + (size_t)(bcol + r) * K + k0 + lc);
            Ws[lc + 0][r] = vw.x; Ws[lc + 1][r] = vw.y;
            Ws[lc + 2][r] = vw.z; Ws[lc + 3][r] = vw.w;
        }
        __syncthreads();
#pragma unroll
        for (int k = 0; k < 16; k++) {
            float4 a0 = *reinterpret_cast<const float4*>(&As[k][tr]);
            float4 a1 = *reinterpret_cast<const float4*>(&As[k][tr + 4]);
            float4 b0 = *reinterpret_cast<const float4*>(&Ws[k][tc]);
            float4 b1 = *reinterpret_cast<const float4*>(&Ws[k][tc + 4]);
            float a[8] = {a0.x, a0.y, a0.z, a0.w, a1.x, a1.y, a1.z, a1.w};
            float b[8] = {b0.x, b0.y, b0.z, b0.w, b1.x, b1.y, b1.z, b1.w};
#pragma unroll
            for (int i = 0; i < 8; i++)
#pragma unroll
                for (int j = 0; j < 8; j++)
                    acc[i][j] += a[i] * b[j];
        }
        __syncthreads();
    }

    float4 bv0 = *reinterpret_cast<const float4*>(bias + bcol + tc);
    float4 bv1 = *reinterpret_cast<const float4*>(bias + bcol + tc + 4);
    float bb[8] = {bv0.x, bv0.y, bv0.z, bv0.w, bv1.x, bv1.y, bv1.z, bv1.w};
#pragma unroll
    for (int i = 0; i < 8; i++) {
        float4 o0 = make_float4(acc[i][0] + bb[0], acc[i][1] + bb[1],
                                acc[i][2] + bb[2], acc[i][3] + bb[3]);
        float4 o1 = make_float4(acc[i][4] + bb[4], acc[i][5] + bb[5],
                                acc[i][6] + bb[6], acc[i][7] + bb[7]);
        float* crow = C + (size_t)(brow + tr + i) * N + bcol + tc;
        *reinterpret_cast<float4*>(crow)     = o0;
        *reinterpret_cast<float4*>(crow + 4) = o1;
    }
}

// ---------------------------------------------------------------------------
// Flash attention (fp32, online softmax). One block = 64 query rows of one
// (b, h). 256 threads: ty = tid/16 -> 4 query rows (ty*4+i);
// tx = tid%16 -> 4 score cols (tx + 16j) / 4 output dims (tx*4+d).
// ---------------------------------------------------------------------------
__global__ __launch_bounds__(256)
void flash_kernel(const float* __restrict__ Qp, const float* __restrict__ Kp,
                  const float* __restrict__ Vp, const int* __restrict__ mask,
                  float* __restrict__ O, int B, int S)
{
    extern __shared__ float sm[];
    const int ST = 68;                       // padded row stride
    float* Qs  = sm;                         // 64*68
    float* Ks  = Qs + 64 * ST;               // 64*68
    float* Vs  = Ks + 64 * ST;               // 64*68
    float* Ps  = Vs + 64 * ST;               // 64*68
    float* msk = Ps + 64 * ST;               // 64

    const int tid = threadIdx.x;
    const int ty  = tid >> 4;
    const int tx  = tid & 15;

    const int b  = blockIdx.y >> 3;
    const int h  = blockIdx.y & 7;
    const int q0 = blockIdx.x * 64;

    const float* Qb = Qp + (size_t)b * S * DMODEL + (size_t)h * DK;
    const float* Kb = Kp + (size_t)b * S * DMODEL + (size_t)h * DK;
    const float* Vb = Vp + (size_t)b * S * DMODEL + (size_t)h * DK;
    const int*   mb = mask + (size_t)b * S;

    // Load Q tile (64 x 64)
#pragma unroll
    for (int i = 0; i < 4; i++) {
        int idx = tid + i * 256;
        int r = idx >> 4;
        int c = (idx & 15) << 2;
        *reinterpret_cast<float4*>(Qs + r * ST + c) =
            *reinterpret_cast<const float4*>(Qb + (size_t)(q0 + r) * DMODEL + c);
    }

    float m_i[4], l_i[4], Oa[4][4];
#pragma unroll
    for (int i = 0; i < 4; i++) {
        m_i[i] = -1e30f; l_i[i] = 0.f;
#pragma unroll
        for (int d = 0; d < 4; d++) Oa[i][d] = 0.f;
    }

    const int nT = S / 64;
    for (int t = 0; t < nT; t++) {
        __syncthreads();   // previous iter's Ps/Vs reads done before overwrite
#pragma unroll
        for (int i = 0; i < 4; i++) {
            int idx = tid + i * 256;
            int r = idx >> 4;
            int c = (idx & 15) << 2;
            *reinterpret_cast<float4*>(Ks + r * ST + c) =
                *reinterpret_cast<const float4*>(Kb + (size_t)(t * 64 + r) * DMODEL + c);
            *reinterpret_cast<float4*>(Vs + r * ST + c) =
                *reinterpret_cast<const float4*>(Vb + (size_t)(t * 64 + r) * DMODEL + c);
        }
        if (tid < 64) msk[tid] = (mb[t * 64 + tid] == 0) ? -1e9f : 0.f;
        __syncthreads();

        // S = Q K^T (cols for this thread: tx + 16j -> conflict-free K reads)
        float s[4][4];
#pragma unroll
        for (int i = 0; i < 4; i++)
#pragma unroll
            for (int j = 0; j < 4; j++) s[i][j] = 0.f;

#pragma unroll
        for (int kk = 0; kk < DK; kk += 4) {
            float4 qv[4], kv[4];
#pragma unroll
            for (int i = 0; i < 4; i++)
                qv[i] = *reinterpret_cast<const float4*>(Qs + (ty * 4 + i) * ST + kk);
#pragma unroll
            for (int j = 0; j < 4; j++)
                kv[j] = *reinterpret_cast<const float4*>(Ks + (tx + 16 * j) * ST + kk);
#pragma unroll
            for (int i = 0; i < 4; i++)
#pragma unroll
                for (int j = 0; j < 4; j++)
                    s[i][j] += qv[i].x * kv[j].x + qv[i].y * kv[j].y +
                               qv[i].z * kv[j].z + qv[i].w * kv[j].w;
        }

        // Online softmax update
#pragma unroll
        for (int i = 0; i < 4; i++) {
#pragma unroll
            for (int j = 0; j < 4; j++)
                s[i][j] = s[i][j] * 0.125f + msk[tx + 16 * j];   // 1/sqrt(64)
            float rmax = fmaxf(fmaxf(s[i][0], s[i][1]), fmaxf(s[i][2], s[i][3]));
#pragma unroll
            for (int off = 8; off >= 1; off >>= 1)
                rmax = fmaxf(rmax, __shfl_xor_sync(0xffffffffu, rmax, off));
            float mnew  = fmaxf(m_i[i], rmax);
            float alpha = __expf(m_i[i] - mnew);
            float rsum = 0.f;
#pragma unroll
            for (int j = 0; j < 4; j++) {
                float p = __expf(s[i][j] - mnew);
                Ps[(ty * 4 + i) * ST + tx + 16 * j] = p;
                rsum += p;
            }
#pragma unroll
            for (int off = 8; off >= 1; off >>= 1)
                rsum += __shfl_xor_sync(0xffffffffu, rsum, off);
            m_i[i] = mnew;
            l_i[i] = l_i[i] * alpha + rsum;
#pragma unroll
            for (int d = 0; d < 4; d++) Oa[i][d] *= alpha;
        }
        __syncthreads();   // Ps complete before PV

        // O += P V  (this thread's output dims: tx*4 .. tx*4+3)
#pragma unroll
        for (int c = 0; c < 64; c += 4) {
            float4 pv[4], vv[4];
#pragma unroll
            for (int i = 0; i < 4; i++)
                pv[i] = *reinterpret_cast<const float4*>(Ps + (ty * 4 + i) * ST + c);
#pragma unroll
            for (int j = 0; j < 4; j++)
                vv[j] = *reinterpret_cast<const float4*>(Vs + (c + j) * ST + tx * 4);
#pragma unroll
            for (int i = 0; i < 4; i++) {
                Oa[i][0] += pv[i].x * vv[0].x + pv[i].y * vv[1].x + pv[i].z * vv[2].x + pv[i].w * vv[3].x;
                Oa[i][1] += pv[i].x * vv[0].y + pv[i].y * vv[1].y + pv[i].z * vv[2].y + pv[i].w * vv[3].y;
                Oa[i][2] += pv[i].x * vv[0].z + pv[i].y * vv[1].z + pv[i].z * vv[2].z + pv[i].w * vv[3].z;
                Oa[i][3] += pv[i].x * vv[0].w + pv[i].y * vv[1].w + pv[i].z * vv[2].w + pv[i].w * vv[3].w;
            }
        }
    }

    // Normalize and write ctx: [b, s, h*64 + d]
#pragma unroll
    for (int i = 0; i < 4; i++) {
        float inv = 1.f / l_i[i];
        float4 o = make_float4(Oa[i][0] * inv, Oa[i][1] * inv,
                               Oa[i][2] * inv, Oa[i][3] * inv);
        *reinterpret_cast<float4*>(
            O + (size_t)(b * S + q0 + ty * 4 + i) * DMODEL + h * DK + tx * 4) = o;
    }
}

// ---------------------------------------------------------------------------
extern "C" void kernel_launch(void* const* d_in, const int* in_sizes, int n_in,
                              void* d_out, int out_size)
{
    const float* q    = (const float*)d_in[0];
    const float* k    = (const float*)d_in[1];
    const float* v    = (const float*)d_in[2];
    const int*   mask = (const int*)  d_in[3];
    const float* Wq   = (const float*)d_in[4];
    const float* bq   = (const float*)d_in[5];
    const float* Wk   = (const float*)d_in[6];
    const float* bk   = (const float*)d_in[7];
    const float* Wv   = (const float*)d_in[8];
    const float* bv   = (const float*)d_in[9];
    const float* Wo   = (const float*)d_in[10];
    const float* bo   = (const float*)d_in[11];

    const int S = SEQ, D = DMODEL;
    const int B = in_sizes[0] / (S * D);
    const int M = B * S;

    float *gQ, *gK, *gV, *gC;
    cudaGetSymbolAddress((void**)&gQ, g_Q);
    cudaGetSymbolAddress((void**)&gK, g_K);
    cudaGetSymbolAddress((void**)&gV, g_V);
    cudaGetSymbolAddress((void**)&gC, g_C);

    dim3 ggrid(D / 128, M / 128);
    gemm_bias_kernel<<<ggrid, 256>>>(q, Wq, bq, gQ, M, D, D);
    gemm_bias_kernel<<<ggrid, 256>>>(k, Wk, bk, gK, M, D, D);
    gemm_bias_kernel<<<ggrid, 256>>>(v, Wv, bv, gV, M, D, D);

    const size_t smem = (size_t)(4 * 64 * 68 + 64) * sizeof(float);
    cudaFuncSetAttribute(flash_kernel, cudaFuncAttributeMaxDynamicSharedMemorySize, (int)smem);
    flash_kernel<<<dim3(S / 64, B * NHEAD), 256, smem>>>(gQ, gK, gV, mask, gC, B, S);

    gemm_bias_kernel<<<ggrid, 256>>>(gC, Wo, bo, (float*)d_out, M, D, D);
}

// round 3
// speedup vs baseline: 1.8555x; 1.8555x over previous
#include <cuda_runtime.h>
#include <cuda_bf16.h>
#include <cstdint>
#include <cstddef>

#define SEQ    4096
#define DMODEL 512
#define NHEAD  8
#define DK     64

// Scratch (static device globals — no allocation in kernel_launch)
__device__ float g_Q[2 * SEQ * DMODEL];
__device__ float g_K[2 * SEQ * DMODEL];
__device__ float g_V[2 * SEQ * DMODEL];
__device__ float g_C[2 * SEQ * DMODEL];

// ---------------------------------------------------------------------------
// helpers
// ---------------------------------------------------------------------------
#define SWZ(o) ((o) ^ (((o) >> 3) & 0x70))   // SW128-style: chunk bits[6:4] ^= row%8

__device__ __forceinline__ uint32_t smem_u32(const void* p) {
    uint32_t a;
    asm("{ .reg .u64 t; cvta.to.shared.u64 t, %1; cvt.u32.u64 %0, t; }" : "=r"(a) : "l"(p));
    return a;
}

__device__ __forceinline__ void ldsm_x4(uint32_t* r, uint32_t addr) {
    asm volatile("ldmatrix.sync.aligned.m8n8.x4.shared.b16 {%0,%1,%2,%3}, [%4];"
                 : "=r"(r[0]), "=r"(r[1]), "=r"(r[2]), "=r"(r[3]) : "r"(addr));
}
__device__ __forceinline__ void ldsm_x2(uint32_t& r0, uint32_t& r1, uint32_t addr) {
    asm volatile("ldmatrix.sync.aligned.m8n8.x2.shared.b16 {%0,%1}, [%2];"
                 : "=r"(r0), "=r"(r1) : "r"(addr));
}
__device__ __forceinline__ void ldsm_x2t(uint32_t& r0, uint32_t& r1, uint32_t addr) {
    asm volatile("ldmatrix.sync.aligned.m8n8.x2.trans.shared.b16 {%0,%1}, [%2];"
                 : "=r"(r0), "=r"(r1) : "r"(addr));
}

// D = A(16x16 bf16) * B(16x8 bf16) + D, fp32 accum
__device__ __forceinline__ void mma16816(float* c, const uint32_t* a, uint32_t b0, uint32_t b1) {
    asm volatile("mma.sync.aligned.m16n8k16.row.col.f32.bf16.bf16.f32 "
                 "{%0,%1,%2,%3}, {%4,%5,%6,%7}, {%8,%9}, {%0,%1,%2,%3};"
                 : "+f"(c[0]), "+f"(c[1]), "+f"(c[2]), "+f"(c[3])
                 : "r"(a[0]), "r"(a[1]), "r"(a[2]), "r"(a[3]), "r"(b0), "r"(b1));
}

// hi/lo bf16 split of a float pair -> packed bf16x2 (low half = first arg)
__device__ __forceinline__ void split2(float a, float b, uint32_t& hi, uint32_t& lo) {
    __nv_bfloat162 hp = __floats2bfloat162_rn(a, b);
    float ar = a - __bfloat162float(hp.x);
    float br = b - __bfloat162float(hp.y);
    __nv_bfloat162 lp = __floats2bfloat162_rn(ar, br);
    hi = *reinterpret_cast<uint32_t*>(&hp);
    lo = *reinterpret_cast<uint32_t*>(&lp);
}

// hi/lo split of 8 consecutive floats -> two uint4 (4x bf16x2 each)
__device__ __forceinline__ void cvt8_hilo(const float* x, uint4& hv, uint4& lv) {
    uint32_t h[4], l[4];
#pragma unroll
    for (int e = 0; e < 4; e++) split2(x[2 * e], x[2 * e + 1], h[e], l[e]);
    hv = make_uint4(h[0], h[1], h[2], h[3]);
    lv = make_uint4(l[0], l[1], l[2], l[3]);
}

// ---------------------------------------------------------------------------
// SMEM layout (byte offsets from 1024-aligned base). Q staging reuses K bufs.
// rows are 64 bf16 = 128 bytes, SW128-swizzled.
// ---------------------------------------------------------------------------
#define OFF_B0   0u        // Q_hi (128 rows) staged; loop uses rows 0-63 as K_hi
#define OFF_B1   16384u    // Q_lo / K_lo
#define OFF_VHI  32768u    // V_hi (64 rows)
#define OFF_VLO  40960u    // V_lo
#define OFF_MSK  49152u    // 64 floats
#define SMEM_BYTES (49408u + 1024u)

// ---------------------------------------------------------------------------
// FA2-style attention on mma.sync bf16 (hi/lo split). CTA = 128 q rows of one
// (b,h), 8 warps x 16 rows. Key tile = 64.
// ---------------------------------------------------------------------------
__global__ __launch_bounds__(256)
void flash_mma(const float* __restrict__ Qp, const float* __restrict__ Kp,
               const float* __restrict__ Vp, const int* __restrict__ mask,
               float* __restrict__ O, int B)
{
    extern __shared__ char dsm[];
    char* sb = (char*)(((uintptr_t)dsm + 1023) & ~(uintptr_t)1023);
    const uint32_t sbase = smem_u32(sb);
    float* mskp = (float*)(sb + OFF_MSK);

    const int tid  = threadIdx.x;
    const int wid  = tid >> 5;
    const int lane = tid & 31;

    const int b  = blockIdx.y >> 3;
    const int h  = blockIdx.y & 7;
    const int q0 = blockIdx.x * 128;

    const float* Qb = Qp + ((size_t)b * SEQ + q0) * DMODEL + h * DK;
    const float* Kb = Kp + (size_t)b * SEQ * DMODEL + h * DK;
    const float* Vb = Vp + (size_t)b * SEQ * DMODEL + h * DK;
    const int*   mb = mask + (size_t)b * SEQ;

    // ---- stage Q (128x64) hi/lo into B0/B1 ----
    {
        const int row = tid >> 1;
        const int c0  = (tid & 1) * 32;
        const float* qr = Qb + (size_t)row * DMODEL + c0;
#pragma unroll
        for (int c = 0; c < 32; c += 8) {
            float x[8];
            *(float4*)&x[0] = *(const float4*)(qr + c);
            *(float4*)&x[4] = *(const float4*)(qr + c + 4);
            uint4 hv, lv; cvt8_hilo(x, hv, lv);
            uint32_t off = SWZ((uint32_t)row * 128u + (uint32_t)(c0 + c) * 2u);
            *(uint4*)(sb + OFF_B0 + off) = hv;
            *(uint4*)(sb + OFF_B1 + off) = lv;
        }
    }
    __syncthreads();

    // ---- Q fragments: 4 k-steps x {a0..a3}, hi and lo ----
    uint32_t qh[4][4], ql[4][4];
    {
        const int r  = wid * 16 + (lane & 15);
        const int cb = (lane >> 4);           // 0: k0-7, 1: k8-15 within k-step
#pragma unroll
        for (int ks = 0; ks < 4; ks++) {
            uint32_t off = SWZ((uint32_t)r * 128u + (uint32_t)(ks * 2 + cb) * 16u);
            ldsm_x4(qh[ks], sbase + OFF_B0 + off);
            ldsm_x4(ql[ks], sbase + OFF_B1 + off);
        }
    }
    __syncthreads();   // everyone done reading Q staging before K overwrites

    float o[8][4];
#pragma unroll
    for (int nb = 0; nb < 8; nb++)
#pragma unroll
        for (int j = 0; j < 4; j++) o[nb][j] = 0.f;
    float m0 = -1e30f, m1 = -1e30f, l0 = 0.f, l1 = 0.f;

    const int nT = SEQ / 64;
    for (int t = 0; t < nT; t++) {
        __syncthreads();  // previous tile fully consumed

        // ---- load K,V tile (64 x 64) hi/lo + mask ----
        {
            const int row = tid >> 2;
            const int c0  = (tid & 3) * 16;
            const float* kr = Kb + (size_t)(t * 64 + row) * DMODEL + c0;
            const float* vr = Vb + (size_t)(t * 64 + row) * DMODEL + c0;
#pragma unroll
            for (int c = 0; c < 16; c += 8) {
                float x[8];
                *(float4*)&x[0] = *(const float4*)(kr + c);
                *(float4*)&x[4] = *(const float4*)(kr + c + 4);
                uint4 hv, lv; cvt8_hilo(x, hv, lv);
                uint32_t off = SWZ((uint32_t)row * 128u + (uint32_t)(c0 + c) * 2u);
                *(uint4*)(sb + OFF_B0 + off) = hv;
                *(uint4*)(sb + OFF_B1 + off) = lv;

                *(float4*)&x[0] = *(const float4*)(vr + c);
                *(float4*)&x[4] = *(const float4*)(vr + c + 4);
                cvt8_hilo(x, hv, lv);
                *(uint4*)(sb + OFF_VHI + off) = hv;
                *(uint4*)(sb + OFF_VLO + off) = lv;
            }
            if (tid < 64) mskp[tid] = (mb[t * 64 + tid] == 0) ? -1e9f : 0.f;
        }
        __syncthreads();

        // ---- S = Q K^T (hi*hi + lo*hi + hi*lo) ----
        float s[8][4];
#pragma unroll
        for (int nb = 0; nb < 8; nb++) {
#pragma unroll
            for (int j = 0; j < 4; j++) s[nb][j] = 0.f;
#pragma unroll
            for (int ks = 0; ks < 4; ks++) {
                const int  krow = nb * 8 + (lane & 7);
                const int  kch  = ks * 2 + ((lane >> 3) & 1);
                uint32_t off = SWZ((uint32_t)krow * 128u + (uint32_t)kch * 16u);
                uint32_t bh0, bh1, bl0, bl1;
                ldsm_x2(bh0, bh1, sbase + OFF_B0 + off);
                ldsm_x2(bl0, bl1, sbase + OFF_B1 + off);
                mma16816(s[nb], qh[ks], bh0, bh1);
                mma16816(s[nb], ql[ks], bh0, bh1);
                mma16816(s[nb], qh[ks], bl0, bl1);
            }
        }

        // ---- online softmax (rows r=lane/4 and r+8) ----
        float rm0 = -1e30f, rm1 = -1e30f;
#pragma unroll
        for (int nb = 0; nb < 8; nb++) {
            float2 mk = *(const float2*)(mskp + nb * 8 + (lane & 3) * 2);
            s[nb][0] = s[nb][0] * 0.125f + mk.x;
            s[nb][1] = s[nb][1] * 0.125f + mk.y;
            s[nb][2] = s[nb][2] * 0.125f + mk.x;
            s[nb][3] = s[nb][3] * 0.125f + mk.y;
            rm0 = fmaxf(rm0, fmaxf(s[nb][0], s[nb][1]));
            rm1 = fmaxf(rm1, fmaxf(s[nb][2], s[nb][3]));
        }
        rm0 = fmaxf(rm0, __shfl_xor_sync(0xffffffffu, rm0, 1));
        rm0 = fmaxf(rm0, __shfl_xor_sync(0xffffffffu, rm0, 2));
        rm1 = fmaxf(rm1, __shfl_xor_sync(0xffffffffu, rm1, 1));
        rm1 = fmaxf(rm1, __shfl_xor_sync(0xffffffffu, rm1, 2));

        const float mn0 = fmaxf(m0, rm0), mn1 = fmaxf(m1, rm1);
        const float a0 = __expf(m0 - mn0), a1 = __expf(m1 - mn1);
        m0 = mn0; m1 = mn1;

        float rs0 = 0.f, rs1 = 0.f;
#pragma unroll
        for (int nb = 0; nb < 8; nb++) {
            s[nb][0] = __expf(s[nb][0] - mn0);
            s[nb][1] = __expf(s[nb][1] - mn0);
            s[nb][2] = __expf(s[nb][2] - mn1);
            s[nb][3] = __expf(s[nb][3] - mn1);
            rs0 += s[nb][0] + s[nb][1];
            rs1 += s[nb][2] + s[nb][3];
        }
        rs0 += __shfl_xor_sync(0xffffffffu, rs0, 1);
        rs0 += __shfl_xor_sync(0xffffffffu, rs0, 2);
        rs1 += __shfl_xor_sync(0xffffffffu, rs1, 1);
        rs1 += __shfl_xor_sync(0xffffffffu, rs1, 2);
        l0 = l0 * a0 + rs0;
        l1 = l1 * a1 + rs1;

#pragma unroll
        for (int nb = 0; nb < 8; nb++) {
            o[nb][0] *= a0; o[nb][1] *= a0;
            o[nb][2] *= a1; o[nb][3] *= a1;
        }

        // ---- P -> bf16 hi/lo fragments (C-frag layout == A-frag layout) ----
        uint32_t ph[8][2], pl[8][2];
#pragma unroll
        for (int nb = 0; nb < 8; nb++) {
            split2(s[nb][0], s[nb][1], ph[nb][0], pl[nb][0]);
            split2(s[nb][2], s[nb][3], ph[nb][1], pl[nb][1]);
        }

        // ---- O += P V (ph*vh + pl*vh + ph*vl) ----
#pragma unroll
        for (int nb = 0; nb < 8; nb++) {
#pragma unroll
            for (int ks = 0; ks < 4; ks++) {
                const int vrow = ks * 16 + (lane & 15);
                uint32_t off = SWZ((uint32_t)vrow * 128u + (uint32_t)nb * 16u);
                uint32_t vh0, vh1, vl0, vl1;
                ldsm_x2t(vh0, vh1, sbase + OFF_VHI + off);
                ldsm_x2t(vl0, vl1, sbase + OFF_VLO + off);
                uint32_t ah[4] = {ph[2 * ks][0], ph[2 * ks][1], ph[2 * ks + 1][0], ph[2 * ks + 1][1]};
                uint32_t al[4] = {pl[2 * ks][0], pl[2 * ks][1], pl[2 * ks + 1][0], pl[2 * ks + 1][1]};
                mma16816(o[nb], ah, vh0, vh1);
                mma16816(o[nb], al, vh0, vh1);
                mma16816(o[nb], ah, vl0, vl1);
            }
        }
    }

    // ---- epilogue ----
    const float i0 = 1.f / l0, i1 = 1.f / l1;
    const int r    = lane >> 2;
    const int cb   = (lane & 3) * 2;
    float* Ob = O + ((size_t)b * SEQ + q0 + wid * 16) * DMODEL + h * DK;
#pragma unroll
    for (int nb = 0; nb < 8; nb++) {
        float2 v0 = make_float2(o[nb][0] * i0, o[nb][1] * i0);
        float2 v1 = make_float2(o[nb][2] * i1, o[nb][3] * i1);
        *(float2*)(Ob + (size_t)r * DMODEL + nb * 8 + cb)       = v0;
        *(float2*)(Ob + (size_t)(r + 8) * DMODEL + nb * 8 + cb) = v1;
    }
}

// ---------------------------------------------------------------------------
// fp32 GEMM with bias (round-1): C = A @ W^T + b
// ---------------------------------------------------------------------------
__global__ __launch_bounds__(256)
void gemm_bias_kernel(const float* __restrict__ A, const float* __restrict__ W,
                      const float* __restrict__ bias, float* __restrict__ C,
                      int M, int N, int K)
{
    __shared__ float As[16][128];
    __shared__ float Ws[16][128];

    const int tid  = threadIdx.x;
    const int brow = blockIdx.y * 128;
    const int bcol = blockIdx.x * 128;
    const int tr   = (tid / 16) * 8;
    const int tc   = (tid % 16) * 8;
    const int lr   = tid / 4;
    const int lc   = (tid % 4) * 4;

    float acc[8][8];
#pragma unroll
    for (int i = 0; i < 8; i++)
#pragma unroll
        for (int j = 0; j < 8; j++) acc[i][j] = 0.f;

    for (int k0 = 0; k0 < K; k0 += 16) {
#pragma unroll
        for (int i = 0; i < 2; i++) {
            int r = lr + i * 64;
            float4 va = *reinterpret_cast<const float4*>(A + (size_t)(brow + r) * K + k0 + lc);
            As[lc + 0][r] = va.x; As[lc + 1][r] = va.y;
            As[lc + 2][r] = va.z; As[lc + 3][r] = va.w;
            float4 vw = *reinterpret_cast<const float4*>(W + (size_t)(bcol + r) * K + k0 + lc);
            Ws[lc + 0][r] = vw.x; Ws[lc + 1][r] = vw.y;
            Ws[lc + 2][r] = vw.z; Ws[lc + 3][r] = vw.w;
        }
        __syncthreads();
#pragma unroll
        for (int k = 0; k < 16; k++) {
            float4 a0 = *reinterpret_cast<const float4*>(&As[k][tr]);
            float4 a1 = *reinterpret_cast<const float4*>(&As[k][tr + 4]);
            float4 b0 = *reinterpret_cast<const float4*>(&Ws[k][tc]);
            float4 b1 = *reinterpret_cast<const float4*>(&Ws[k][tc + 4]);
            float a[8] = {a0.x, a0.y, a0.z, a0.w, a1.x, a1.y, a1.z, a1.w};
            float b[8] = {b0.x, b0.y, b0.z, b0.w, b1.x, b1.y, b1.z, b1.w};
#pragma unroll
            for (int i = 0; i < 8; i++)
#pragma unroll
                for (int j = 0; j < 8; j++)
                    acc[i][j] += a[i] * b[j];
        }
        __syncthreads();
    }

    float4 bv0 = *reinterpret_cast<const float4*>(bias + bcol + tc);
    float4 bv1 = *reinterpret_cast<const float4*>(bias + bcol + tc + 4);
    float bb[8] = {bv0.x, bv0.y, bv0.z, bv0.w, bv1.x, bv1.y, bv1.z, bv1.w};
#pragma unroll
    for (int i = 0; i < 8; i++) {
        float4 o0 = make_float4(acc[i][0] + bb[0], acc[i][1] + bb[1],
                                acc[i][2] + bb[2], acc[i][3] + bb[3]);
        float4 o1 = make_float4(acc[i][4] + bb[4], acc[i][5] + bb[5],
                                acc[i][6] + bb[6], acc[i][7] + bb[7]);
        float* crow = C + (size_t)(brow + tr + i) * N + bcol + tc;
        *reinterpret_cast<float4*>(crow)     = o0;
        *reinterpret_cast<float4*>(crow + 4) = o1;
    }
}

// ---------------------------------------------------------------------------
extern "C" void kernel_launch(void* const* d_in, const int* in_sizes, int n_in,
                              void* d_out, int out_size)
{
    const float* q    = (const float*)d_in[0];
    const float* k    = (const float*)d_in[1];
    const float* v    = (const float*)d_in[2];
    const int*   mask = (const int*)  d_in[3];
    const float* Wq   = (const float*)d_in[4];
    const float* bq   = (const float*)d_in[5];
    const float* Wk   = (const float*)d_in[6];
    const float* bk   = (const float*)d_in[7];
    const float* Wv   = (const float*)d_in[8];
    const float* bv   = (const float*)d_in[9];
    const float* Wo   = (const float*)d_in[10];
    const float* bo   = (const float*)d_in[11];

    const int S = SEQ, D = DMODEL;
    const int B = in_sizes[0] / (S * D);
    const int M = B * S;

    float *gQ, *gK, *gV, *gC;
    cudaGetSymbolAddress((void**)&gQ, g_Q);
    cudaGetSymbolAddress((void**)&gK, g_K);
    cudaGetSymbolAddress((void**)&gV, g_V);
    cudaGetSymbolAddress((void**)&gC, g_C);

    dim3 ggrid(D / 128, M / 128);
    gemm_bias_kernel<<<ggrid, 256>>>(q, Wq, bq, gQ, M, D, D);
    gemm_bias_kernel<<<ggrid, 256>>>(k, Wk, bk, gK, M, D, D);
    gemm_bias_kernel<<<ggrid, 256>>>(v, Wv, bv, gV, M, D, D);

    cudaFuncSetAttribute(flash_mma, cudaFuncAttributeMaxDynamicSharedMemorySize, SMEM_BYTES);
    flash_mma<<<dim3(S / 128, B * NHEAD), 256, SMEM_BYTES>>>(gQ, gK, gV, mask, gC, B);

    gemm_bias_kernel<<<ggrid, 256>>>(gC, Wo, bo, (float*)d_out, M, D, D);
}